// round 1
// baseline (speedup 1.0000x reference)
#include <cuda_runtime.h>
#include <utility>
#include <cstddef>

// Problem constants (fixed by the reference: N_COLS=16, ADD=3)
#define NC    16          // input columns
#define NTOT  696         // 16 + C(16,2)=120 + C(16,3)=560
#define TPB   128         // threads per block == rows per block
#define CHUNK 87          // output-column chunk width (8 * 87 = 696)
#define NCHUNK 8
#define SPAD  129         // row stride in transposed smem tile (odd -> conflict-free)

// Compile-time decode of output column g -> (i, j, k) subset indices.
// sel: 0 -> i, 1 -> j, 2 -> k.  Returns NC (=16) as "unused" sentinel.
__host__ __device__ constexpr int decode(int g, int sel) {
    if (g < NC) return sel == 0 ? g : NC;          // passthrough columns
    g -= NC;
    if (g < 120) {                                  // pairs, lexicographic
        int c = 0;
        for (int a = 0; a < NC; a++)
            for (int b = a + 1; b < NC; b++) {
                if (c == g) return sel == 0 ? a : (sel == 1 ? b : NC);
                c++;
            }
    } else {                                        // triples, lexicographic
        g -= 120;
        int c = 0;
        for (int a = 0; a < NC; a++)
            for (int b = a + 1; b < NC; b++)
                for (int d = b + 1; d < NC; d++) {
                    if (c == g) return sel == 0 ? a : (sel == 1 ? b : d);
                    c++;
                }
    }
    return NC;
}

// One output term with fully compile-time indices -> v[] stays in registers.
// Association (v[i]*v[j])*v[k] lets ptxas CSE the pair product across the
// lexicographic run of triples sharing (i, j).
template <int G>
__device__ __forceinline__ float term(const float (&v)[NC + 1]) {
    constexpr int i = decode(G, 0);
    constexpr int j = decode(G, 1);
    constexpr int k = decode(G, 2);
    float r = v[i];
    if constexpr (j < NC) r = r * v[j];
    if constexpr (k < NC) r = r * v[k];
    return r;
}

// Compute this thread's row for output columns [C0, C0+CHUNK) into the
// transposed smem tile: s[col_local * SPAD + tid]. Conflict-free STS
// (bank = (col*129 + tid) % 32 = (col + tid) % 32, tid varies per lane).
template <int C0, int... I>
__device__ __forceinline__ void compute_chunk(const float (&v)[NC + 1], float* s, int tid,
                                              std::integer_sequence<int, I...>) {
    ((s[I * SPAD + tid] = term<C0 + I>(v)), ...);
}

// Full chunk: compute -> barrier -> coalesced copy smem -> gmem -> barrier.
// Copy mapping: linear idx = kk*128 + tid over CHUNK*128 elements,
// r = idx / CHUNK (row within block), cl = idx % CHUNK (column in chunk).
// Consecutive lanes -> consecutive cl in the same row -> coalesced STG.32
// and conflict-free LDS (bank = cl + r mod 32).
template <int C0>
__device__ __forceinline__ void process_chunk(const float (&v)[NC + 1], float* s, int tid,
                                              float* outr, int rmax) {
    compute_chunk<C0>(v, s, tid, std::make_integer_sequence<int, CHUNK>{});
    __syncthreads();
#pragma unroll 4
    for (int kk = 0; kk < CHUNK; kk++) {
        int idx = kk * TPB + tid;
        int r   = idx / CHUNK;
        int cl  = idx - r * CHUNK;
        if (r < rmax)
            outr[(size_t)r * NTOT + (C0 + cl)] = s[cl * SPAD + r];
    }
    __syncthreads();
}

__global__ void __launch_bounds__(TPB)
algebraic_kernel(const float* __restrict__ x, float* __restrict__ out, int nrows) {
    __shared__ float s[CHUNK * SPAD];   // 87 * 129 * 4 = 44,892 B (static, < 48 KB)

    const int tid  = threadIdx.x;
    const int row0 = blockIdx.x * TPB;
    const int row  = row0 + tid;

    float v[NC + 1];
    if (row < nrows) {
        const float4* xp = reinterpret_cast<const float4*>(x) + (size_t)row * (NC / 4);
        float4 a = xp[0], b = xp[1], c = xp[2], d = xp[3];
        v[0]  = a.x; v[1]  = a.y; v[2]  = a.z; v[3]  = a.w;
        v[4]  = b.x; v[5]  = b.y; v[6]  = b.z; v[7]  = b.w;
        v[8]  = c.x; v[9]  = c.y; v[10] = c.z; v[11] = c.w;
        v[12] = d.x; v[13] = d.y; v[14] = d.z; v[15] = d.w;
    } else {
#pragma unroll
        for (int q = 0; q < NC; q++) v[q] = 0.0f;
    }
    v[NC] = 1.0f;  // sentinel (unused-index slot; folded away by if-constexpr anyway)

    float*    outr = out + (size_t)row0 * NTOT;
    const int rmax = (nrows - row0 < TPB) ? (nrows - row0) : TPB;

    process_chunk<0 * CHUNK>(v, s, tid, outr, rmax);
    process_chunk<1 * CHUNK>(v, s, tid, outr, rmax);
    process_chunk<2 * CHUNK>(v, s, tid, outr, rmax);
    process_chunk<3 * CHUNK>(v, s, tid, outr, rmax);
    process_chunk<4 * CHUNK>(v, s, tid, outr, rmax);
    process_chunk<5 * CHUNK>(v, s, tid, outr, rmax);
    process_chunk<6 * CHUNK>(v, s, tid, outr, rmax);
    process_chunk<7 * CHUNK>(v, s, tid, outr, rmax);
}

extern "C" void kernel_launch(void* const* d_in, const int* in_sizes, int n_in,
                              void* d_out, int out_size) {
    const float* x   = (const float*)d_in[0];
    float*       out = (float*)d_out;
    const int nrows  = in_sizes[0] / NC;                 // 262144
    const int blocks = (nrows + TPB - 1) / TPB;          // 2048
    algebraic_kernel<<<blocks, TPB>>>(x, out, nrows);
}

// round 2
// speedup vs baseline: 1.1130x; 1.1130x over previous
#include <cuda_runtime.h>
#include <utility>
#include <cstddef>

// Problem constants (fixed by the reference: N_COLS=16, ADD=3)
#define NC     16         // input columns
#define NTOT   696        // 16 + C(16,2)=120 + C(16,3)=560
#define NTOT4  174        // NTOT / 4 (output row in float4 units)
#define TPB    128        // threads per block == rows per block
#define SPAD4  17         // smem row stride in float4 units (odd -> conflict-free)

// Compile-time decode of output column g -> (i, j, k) subset indices.
// sel: 0 -> i, 1 -> j, 2 -> k.  Returns NC (=16) as "unused" sentinel.
__host__ __device__ constexpr int decode(int g, int sel) {
    if (g < NC) return sel == 0 ? g : NC;          // passthrough columns
    g -= NC;
    if (g < 120) {                                  // pairs, lexicographic
        int c = 0;
        for (int a = 0; a < NC; a++)
            for (int b = a + 1; b < NC; b++) {
                if (c == g) return sel == 0 ? a : (sel == 1 ? b : NC);
                c++;
            }
    } else {                                        // triples, lexicographic
        g -= 120;
        int c = 0;
        for (int a = 0; a < NC; a++)
            for (int b = a + 1; b < NC; b++)
                for (int d = b + 1; d < NC; d++) {
                    if (c == g) return sel == 0 ? a : (sel == 1 ? b : d);
                    c++;
                }
    }
    return NC;
}

// One output term with fully compile-time indices -> v[] stays in registers.
// Association (v[i]*v[j])*v[k] lets ptxas CSE the pair product across the
// lexicographic run of triples sharing (i, j).
template <int G>
__device__ __forceinline__ float term(const float (&v)[NC]) {
    constexpr int i = decode(G, 0);
    constexpr int j = decode(G, 1);
    constexpr int k = decode(G, 2);
    float r = v[i];
    if constexpr (j < NC) r = r * v[j];
    if constexpr (k < NC) r = r * v[k];
    return r;
}

// Compute this thread's row for float4 output columns [C04, C04+NF4) into
// smem: s4[tid * SPAD4 + c].  STS.128 with lane stride 17 f4 = 272 B
// -> bank-start (4*tid) % 32, distinct within each 8-lane phase: conflict-free.
template <int C04, int NF4, int... I>
__device__ __forceinline__ void compute_chunk(const float (&v)[NC], float4* s4, int tid,
                                              std::integer_sequence<int, I...>) {
    ((s4[tid * SPAD4 + I] = make_float4(term<4 * (C04 + I) + 0>(v),
                                        term<4 * (C04 + I) + 1>(v),
                                        term<4 * (C04 + I) + 2>(v),
                                        term<4 * (C04 + I) + 3>(v))), ...);
}

// Full chunk: compute -> barrier -> coalesced float4 copy smem -> gmem -> barrier.
// Copy mapping: idx = kk*TPB + tid over TPB*NF4 float4s; r = idx / NF4,
// c = idx % NF4.  For NF4 = 16 this is shift+mask (no integer divide).
// LDS.128 consecutive addresses (conflict-free); STG.128: 16 lanes cover a
// 256 B contiguous run per row -> fully dense sectors.
template <int C04, int NF4>
__device__ __forceinline__ void process_chunk(const float (&v)[NC], float4* s4, int tid,
                                              float4* __restrict__ oblk) {
    compute_chunk<C04, NF4>(v, s4, tid, std::make_integer_sequence<int, NF4>{});
    __syncthreads();
#pragma unroll
    for (int kk = 0; kk < NF4; kk++) {
        int idx = kk * TPB + tid;
        int r   = idx / NF4;            // shift for NF4=16
        int c   = idx - r * NF4;        // mask for NF4=16
        oblk[(size_t)r * NTOT4 + (C04 + c)] = s4[r * SPAD4 + c];
    }
    __syncthreads();
}

__global__ void __launch_bounds__(TPB, 6)
algebraic_kernel(const float* __restrict__ x, float4* __restrict__ out4) {
    __shared__ float4 s4[TPB * SPAD4];   // 128 * 17 * 16 = 34,816 B -> 6 blocks/SM

    const int tid  = threadIdx.x;
    const size_t row0 = (size_t)blockIdx.x * TPB;

    float v[NC];
    {
        const float4* xp = reinterpret_cast<const float4*>(x) + (row0 + tid) * (NC / 4);
        float4 a = xp[0], b = xp[1], c = xp[2], d = xp[3];
        v[0]  = a.x; v[1]  = a.y; v[2]  = a.z; v[3]  = a.w;
        v[4]  = b.x; v[5]  = b.y; v[6]  = b.z; v[7]  = b.w;
        v[8]  = c.x; v[9]  = c.y; v[10] = c.z; v[11] = c.w;
        v[12] = d.x; v[13] = d.y; v[14] = d.z; v[15] = d.w;
    }

    float4* oblk = out4 + row0 * NTOT4;

    // 10 chunks of 16 float4 columns + final 14  (10*16 + 14 = 174 = 696/4)
    process_chunk<  0, 16>(v, s4, tid, oblk);
    process_chunk< 16, 16>(v, s4, tid, oblk);
    process_chunk< 32, 16>(v, s4, tid, oblk);
    process_chunk< 48, 16>(v, s4, tid, oblk);
    process_chunk< 64, 16>(v, s4, tid, oblk);
    process_chunk< 80, 16>(v, s4, tid, oblk);
    process_chunk< 96, 16>(v, s4, tid, oblk);
    process_chunk<112, 16>(v, s4, tid, oblk);
    process_chunk<128, 16>(v, s4, tid, oblk);
    process_chunk<144, 16>(v, s4, tid, oblk);
    process_chunk<160, 14>(v, s4, tid, oblk);
}

extern "C" void kernel_launch(void* const* d_in, const int* in_sizes, int n_in,
                              void* d_out, int out_size) {
    const float* x    = (const float*)d_in[0];
    float4*      out4 = (float4*)d_out;
    const int nrows   = in_sizes[0] / NC;              // 262144 (multiple of 128)
    const int blocks  = nrows / TPB;                   // 2048
    algebraic_kernel<<<blocks, TPB>>>(x, out4);
}

// round 3
// speedup vs baseline: 1.1333x; 1.0183x over previous
#include <cuda_runtime.h>
#include <utility>
#include <cstddef>

// Problem constants (fixed by the reference: N_COLS=16, ADD=3)
#define NC     16         // input columns
#define NTOT   696        // 16 + C(16,2)=120 + C(16,3)=560
#define NTOT4  174        // NTOT / 4 (output row in float4 units)
#define TPB    128        // threads per block == rows per block
#define WROWS  32         // rows per warp (one row per lane)
#define SPAD4  9          // warp-subtile row stride in float4 units
// stride 9 f4 = 36 words == 4 (mod 32): conflict-free for both STS.128 and
// LDS.128 under the 8-lane-per-subphase shared-memory datapath.

// Compile-time decode of output column g -> (i, j, k) subset indices.
// sel: 0 -> i, 1 -> j, 2 -> k.  Returns NC (=16) as "unused" sentinel.
__host__ __device__ constexpr int decode(int g, int sel) {
    if (g < NC) return sel == 0 ? g : NC;          // passthrough columns
    g -= NC;
    if (g < 120) {                                  // pairs, lexicographic
        int c = 0;
        for (int a = 0; a < NC; a++)
            for (int b = a + 1; b < NC; b++) {
                if (c == g) return sel == 0 ? a : (sel == 1 ? b : NC);
                c++;
            }
    } else {                                        // triples, lexicographic
        g -= 120;
        int c = 0;
        for (int a = 0; a < NC; a++)
            for (int b = a + 1; b < NC; b++)
                for (int d = b + 1; d < NC; d++) {
                    if (c == g) return sel == 0 ? a : (sel == 1 ? b : d);
                    c++;
                }
    }
    return NC;
}

// One output term with fully compile-time indices -> v[] stays in registers.
// Association (v[i]*v[j])*v[k] lets ptxas CSE the pair product across the
// lexicographic run of triples sharing (i, j).
template <int G>
__device__ __forceinline__ float term(const float (&v)[NC]) {
    constexpr int i = decode(G, 0);
    constexpr int j = decode(G, 1);
    constexpr int k = decode(G, 2);
    float r = v[i];
    if constexpr (j < NC) r = r * v[j];
    if constexpr (k < NC) r = r * v[k];
    return r;
}

// Lane computes its own row's float4 columns [C04, C04+NF4) into the warp's
// private subtile at sw[lane * SPAD4 + c].
template <int C04, int NF4, int... I>
__device__ __forceinline__ void compute_chunk(const float (&v)[NC], float4* sw, int lane,
                                              std::integer_sequence<int, I...>) {
    ((sw[lane * SPAD4 + I] = make_float4(term<4 * (C04 + I) + 0>(v),
                                         term<4 * (C04 + I) + 1>(v),
                                         term<4 * (C04 + I) + 2>(v),
                                         term<4 * (C04 + I) + 3>(v))), ...);
}

// Warp-local phase: compute -> syncwarp -> coalesced copy -> syncwarp.
// Copy mapping over the 32 x NF4 subtile: lin = k*32 + lane, r = lin / NF4,
// c = lin % NF4 (compile-time NF4 -> mul/shift, no divide). Lanes sharing a
// row are consecutive in c -> dense 16B-granular STG.128 runs; LDS.128
// conflict-free per the stride-9 analysis above.
template <int C04, int NF4>
__device__ __forceinline__ void process_chunk(const float (&v)[NC], float4* sw, int lane,
                                              float4* __restrict__ owarp) {
    compute_chunk<C04, NF4>(v, sw, lane, std::make_integer_sequence<int, NF4>{});
    __syncwarp();
#pragma unroll
    for (int k = 0; k < NF4; k++) {
        int lin = k * 32 + lane;
        int r   = lin / NF4;
        int c   = lin - r * NF4;
        owarp[(size_t)r * NTOT4 + (C04 + c)] = sw[r * SPAD4 + c];
    }
    __syncwarp();
}

__global__ void __launch_bounds__(TPB, 8)
algebraic_kernel(const float* __restrict__ x, float4* __restrict__ out4) {
    // 4 warps x 32 rows x 9 f4 x 16 B = 18,432 B -> 8 blocks/SM (reg-capped)
    __shared__ float4 s4[4][WROWS * SPAD4];

    const int tid   = threadIdx.x;
    const int lane  = tid & 31;
    const int warp  = tid >> 5;
    const size_t row0 = (size_t)blockIdx.x * TPB;          // block's first row

    float v[NC];
    {
        const float4* xp = reinterpret_cast<const float4*>(x) + (row0 + tid) * (NC / 4);
        float4 a = xp[0], b = xp[1], c = xp[2], d = xp[3];
        v[0]  = a.x; v[1]  = a.y; v[2]  = a.z; v[3]  = a.w;
        v[4]  = b.x; v[5]  = b.y; v[6]  = b.z; v[7]  = b.w;
        v[8]  = c.x; v[9]  = c.y; v[10] = c.z; v[11] = c.w;
        v[12] = d.x; v[13] = d.y; v[14] = d.z; v[15] = d.w;
    }

    float4* sw    = s4[warp];
    float4* owarp = out4 + (row0 + (size_t)warp * WROWS) * NTOT4;

    // 21 phases of 8 float4 columns + final 6  (21*8 + 6 = 174 = 696/4)
    process_chunk<  0, 8>(v, sw, lane, owarp);
    process_chunk<  8, 8>(v, sw, lane, owarp);
    process_chunk< 16, 8>(v, sw, lane, owarp);
    process_chunk< 24, 8>(v, sw, lane, owarp);
    process_chunk< 32, 8>(v, sw, lane, owarp);
    process_chunk< 40, 8>(v, sw, lane, owarp);
    process_chunk< 48, 8>(v, sw, lane, owarp);
    process_chunk< 56, 8>(v, sw, lane, owarp);
    process_chunk< 64, 8>(v, sw, lane, owarp);
    process_chunk< 72, 8>(v, sw, lane, owarp);
    process_chunk< 80, 8>(v, sw, lane, owarp);
    process_chunk< 88, 8>(v, sw, lane, owarp);
    process_chunk< 96, 8>(v, sw, lane, owarp);
    process_chunk<104, 8>(v, sw, lane, owarp);
    process_chunk<112, 8>(v, sw, lane, owarp);
    process_chunk<120, 8>(v, sw, lane, owarp);
    process_chunk<128, 8>(v, sw, lane, owarp);
    process_chunk<136, 8>(v, sw, lane, owarp);
    process_chunk<144, 8>(v, sw, lane, owarp);
    process_chunk<152, 8>(v, sw, lane, owarp);
    process_chunk<160, 8>(v, sw, lane, owarp);
    process_chunk<168, 6>(v, sw, lane, owarp);
}

extern "C" void kernel_launch(void* const* d_in, const int* in_sizes, int n_in,
                              void* d_out, int out_size) {
    const float* x    = (const float*)d_in[0];
    float4*      out4 = (float4*)d_out;
    const int nrows   = in_sizes[0] / NC;              // 262144 (multiple of 128)
    const int blocks  = nrows / TPB;                   // 2048
    algebraic_kernel<<<blocks, TPB>>>(x, out4);
}